// round 12
// baseline (speedup 1.0000x reference)
#include <cuda_runtime.h>
#include <cstdint>

// ---------------- problem constants ----------------
#define B_SZ   32
#define CIN    128
#define H_IN   112
#define W_IN   112
#define COUT   256
#define OHW    55
#define STRIDE 2
#define M_TOT  (B_SZ * OHW * OHW)   // 96800
#define K_TOT  (CIN * 9)            // 1152
#define OPIX   (OHW * OHW)          // 3025
#define INHW   (H_IN * W_IN)        // 12544

// ---------------- GEMM tiling ----------------
#define BM 128
#define BN 256
#define BK 32
#define NT 512
#define KTILES (K_TOT / BK)         // 36
#define NSTAGE 3

#define ASTRIDE 36
#define BSTRIDE 36
#define A_TILE_F (BM * ASTRIDE)     // 4608 floats
#define B_TILE_F (BN * BSTRIDE)     // 9216 floats
#define STAGE_F  (A_TILE_F + B_TILE_F)
#define SMEM_BYTES (NSTAGE * STAGE_F * 4)   // 165888

// permutation of 32-k group: k = step*8 + half*4 + qid -> pos = qid*8 + step*2 + half
__host__ __device__ __forceinline__ int kperm(int k) {
    return (k & 3) * 8 + ((k >> 3) << 1) + ((k >> 2) & 1);
}

// pre-converted (tf32), K-reordered (k' = rs*128 + cin), kperm'd weights
__device__ float g_wperm[COUT * K_TOT];

__device__ __forceinline__ uint32_t smem_u32(const void* p) {
    uint32_t a;
    asm("{ .reg .u64 t; cvta.to.shared.u64 t, %1; cvt.u32.u64 %0, t; }" : "=r"(a) : "l"(p));
    return a;
}
__device__ __forceinline__ uint32_t to_tf32(float f) {
    uint32_t u;
    asm("cvt.rna.tf32.f32 %0, %1;" : "=r"(u) : "f"(f));
    return u;
}

#define CP_ASYNC4(dst, src, sz) \
    asm volatile("cp.async.ca.shared.global [%0], [%1], 4, %2;" \
                 :: "r"(dst), "l"(src), "r"(sz) : "memory")
#define CP_ASYNC16(dst, src) \
    asm volatile("cp.async.cg.shared.global [%0], [%1], 16;" \
                 :: "r"(dst), "l"(src) : "memory")
#define CP_COMMIT()  asm volatile("cp.async.commit_group;" ::: "memory")
#define CP_WAIT2()   asm volatile("cp.async.wait_group 2;"  ::: "memory")
#define CP_WAIT1()   asm volatile("cp.async.wait_group 1;"  ::: "memory")
#define CP_WAIT0()   asm volatile("cp.async.wait_group 0;"  ::: "memory")

__device__ __forceinline__ void mma_tf32(float& c0, float& c1, float& c2, float& c3,
                                         uint32_t a0, uint32_t a1, uint32_t a2, uint32_t a3,
                                         uint32_t b0, uint32_t b1) {
    asm volatile("mma.sync.aligned.m16n8k8.row.col.f32.tf32.tf32.f32 "
                 "{%0,%1,%2,%3}, {%4,%5,%6,%7}, {%8,%9}, {%0,%1,%2,%3};"
                 : "+f"(c0), "+f"(c1), "+f"(c2), "+f"(c3)
                 : "r"(a0), "r"(a1), "r"(a2), "r"(a3), "r"(b0), "r"(b1));
}

// ---------------- weight pre-convert / K-reorder / permute ----------------
__global__ void prep_weights_kernel(const float* __restrict__ w)
{
    const int idx = blockIdx.x * blockDim.x + threadIdx.x;
    if (idx < COUT * K_TOT) {
        const int n   = idx / K_TOT;
        const int k   = idx - n * K_TOT;   // original: cin*9 + rs
        const int cin = k / 9;
        const int rs  = k - cin * 9;
        const int nk  = rs * CIN + cin;    // new K-order
        g_wperm[n * K_TOT + (nk & ~31) + kperm(nk & 31)] =
            __uint_as_float(to_tf32(w[idx]));
    }
}

// ---------------- main implicit-GEMM kernel ----------------
__global__ __launch_bounds__(NT, 1)
void conv_mma_tf32_kernel(const float* __restrict__ x,
                          float* __restrict__ out)
{
    extern __shared__ float sm[];
    const uint32_t sbase = smem_u32(sm);

    const int tid  = threadIdx.x;
    const int lane = tid & 31;
    const int wid  = tid >> 5;      // 0..15
    const int gid  = lane >> 2;     // 0..7
    const int qid  = lane & 3;      // 0..3
    const int warp_m = wid & 3;     // 0..3 -> m offset *32
    const int warp_n = wid >> 2;    // 0..3 -> n offset *64
    const int m0 = blockIdx.x * BM;

    // ---- A gather: thread owns m-row = tid&127, 8 consecutive cin ----
    const int  mRow = tid & 127;
    const int  q8   = tid >> 7;     // 0..3 -> 8-k quarter
    const int  mG     = m0 + mRow;
    const bool mValid = (mG < M_TOT);
    const int  srcsz  = mValid ? 4 : 0;
    const int  mc  = mValid ? mG : (M_TOT - 1);
    const int  bA  = mc / OPIX;
    const int  rA  = mc - bA * OPIX;
    const int  ohA = rA / OHW;
    const int  owA = rA - ohA * OHW;
    const float* xrow = x + (size_t)bA * CIN * INHW
                          + (size_t)(ohA * STRIDE) * W_IN + owA * STRIDE;

    auto load_a = [&](int buf, int kt) {
        const int rs      = kt >> 2;           // 0..8, shared by whole tile
        const int cinbase = (kt & 3) * BK;
        const int r       = rs / 3;
        const int s       = rs - r * 3;
        const float* base = xrow + (size_t)(cinbase + q8 * 8) * INHW + r * W_IN + s;
        // local k = q8*8 + j  ->  pos = (j&3)*8 + q8*2 + ((j>>2)&1)
        const uint32_t dst0 = sbase + (uint32_t)(buf * STAGE_F + mRow * ASTRIDE + q8 * 2) * 4u;
        #pragma unroll
        for (int j = 0; j < 8; j++) {
            const int posj = (j & 3) * 8 + ((j >> 2) & 1);
            CP_ASYNC4(dst0 + 4u * (uint32_t)posj, base + (size_t)j * INHW, srcsz);
        }
    };
    auto load_b = [&](int buf, int kt) {
        #pragma unroll
        for (int p = 0; p < 4; p++) {
            const int idx = tid + NT * p;
            const int row = idx >> 3;          // 0..255
            const int q   = idx & 7;
            const float* g = g_wperm + (size_t)row * K_TOT + kt * BK + q * 4;
            const uint32_t dst = sbase +
                (uint32_t)(buf * STAGE_F + A_TILE_F + row * BSTRIDE + q * 4) * 4u;
            CP_ASYNC16(dst, g);
        }
    };

    float acc[2][8][4];
    #pragma unroll
    for (int i = 0; i < 2; i++)
        #pragma unroll
        for (int j = 0; j < 8; j++)
            #pragma unroll
            for (int e = 0; e < 4; e++)
                acc[i][j][e] = 0.0f;

    // ---- prologue: prime 3 stages ----
    load_a(0, 0); load_b(0, 0); CP_COMMIT();
    load_a(1, 1); load_b(1, 1); CP_COMMIT();
    load_a(2, 2); load_b(2, 2); CP_COMMIT();

    int buf = 0;
    for (int kt = 0; kt < KTILES; kt++) {
        if (kt <= KTILES - 3)      CP_WAIT2();
        else if (kt == KTILES - 2) CP_WAIT1();
        else                       CP_WAIT0();
        __syncthreads();

        const float* A  = sm + buf * STAGE_F;
        const float* Bt = A + A_TILE_F;

        #pragma unroll
        for (int sp = 0; sp < 2; sp++) {          // step pairs
            // load + convert A fragments for both 16-row tiles, both k-steps
            uint32_t ua[2][2][4];                  // [mt][h][4]
            #pragma unroll
            for (int mt = 0; mt < 2; mt++) {
                const float4 p0 = *(const float4*)(A + (warp_m * 32 + mt * 16 + gid) * ASTRIDE + qid * 8 + sp * 4);
                const float4 p1 = *(const float4*)(A + (warp_m * 32 + mt * 16 + gid + 8) * ASTRIDE + qid * 8 + sp * 4);
                ua[mt][0][0] = to_tf32(p0.x);
                ua[mt][0][1] = to_tf32(p1.x);
                ua[mt][0][2] = to_tf32(p0.y);
                ua[mt][0][3] = to_tf32(p1.y);
                ua[mt][1][0] = to_tf32(p0.z);
                ua[mt][1][1] = to_tf32(p1.z);
                ua[mt][1][2] = to_tf32(p0.w);
                ua[mt][1][3] = to_tf32(p1.w);
            }
            #pragma unroll
            for (int nt = 0; nt < 8; nt++) {
                const float4 bv = *(const float4*)(Bt + (warp_n * 64 + nt * 8 + gid) * BSTRIDE + qid * 8 + sp * 4);
                #pragma unroll
                for (int mt = 0; mt < 2; mt++) {
                    mma_tf32(acc[mt][nt][0], acc[mt][nt][1], acc[mt][nt][2], acc[mt][nt][3],
                             ua[mt][0][0], ua[mt][0][1], ua[mt][0][2], ua[mt][0][3],
                             __float_as_uint(bv.x), __float_as_uint(bv.y));
                    mma_tf32(acc[mt][nt][0], acc[mt][nt][1], acc[mt][nt][2], acc[mt][nt][3],
                             ua[mt][1][0], ua[mt][1][1], ua[mt][1][2], ua[mt][1][3],
                             __float_as_uint(bv.z), __float_as_uint(bv.w));
                }
            }
        }
        __syncthreads();

        if (kt + 3 < KTILES) {
            load_a(buf, kt + 3);
            load_b(buf, kt + 3);
            CP_COMMIT();
        }
        buf = (buf == NSTAGE - 1) ? 0 : buf + 1;
    }

    // ---- epilogue: direct register -> gmem scatter ----
    #pragma unroll
    for (int mt = 0; mt < 2; mt++) {
        const int mb = m0 + warp_m * 32 + mt * 16;
        #pragma unroll
        for (int half = 0; half < 2; half++) {
            const int m = mb + gid + half * 8;
            if (m < M_TOT) {
                const int b2  = m / OPIX;
                const int r2  = m - b2 * OPIX;
                const int oh2 = r2 / OHW;
                const int ow2 = r2 - oh2 * OHW;
                float* op = out + (size_t)b2 * COUT * OPIX + (size_t)oh2 * OHW + ow2;
                const int ncol0 = warp_n * 64 + qid * 2;
                #pragma unroll
                for (int nt = 0; nt < 8; nt++) {
                    const int n = ncol0 + nt * 8;
                    op[(size_t)n * OPIX]       = acc[mt][nt][half * 2 + 0];
                    op[(size_t)(n + 1) * OPIX] = acc[mt][nt][half * 2 + 1];
                }
            }
        }
    }
}

extern "C" void kernel_launch(void* const* d_in, const int* in_sizes, int n_in,
                              void* d_out, int out_size)
{
    const float* x = (const float*)d_in[0];
    const float* w = (const float*)d_in[1];
    float* out = (float*)d_out;

    cudaFuncSetAttribute(conv_mma_tf32_kernel,
                         cudaFuncAttributeMaxDynamicSharedMemorySize, SMEM_BYTES);

    prep_weights_kernel<<<(COUT * K_TOT + 255) / 256, 256>>>(w);

    const int grid = (M_TOT + BM - 1) / BM;   // 757
    conv_mma_tf32_kernel<<<grid, NT, SMEM_BYTES>>>(x, out);
}

// round 13
// speedup vs baseline: 1.8007x; 1.8007x over previous
#include <cuda_runtime.h>
#include <cstdint>

// ---------------- problem constants ----------------
#define B_SZ   32
#define CIN    128
#define H_IN   112
#define W_IN   112
#define COUT   256
#define OHW    55
#define STRIDE 2
#define M_TOT  (B_SZ * OHW * OHW)   // 96800
#define K_TOT  (CIN * 9)            // 1152
#define OPIX   (OHW * OHW)          // 3025
#define INHW   (H_IN * W_IN)        // 12544

// ---------------- GEMM tiling ----------------
#define BM 128
#define BN 256
#define BK 32
#define NT 256
#define KTILES (K_TOT / BK)         // 36
#define NSTAGE 4
#define PAIRED_TILES 24             // tiles 0..23: 16 cins x s{0,1}; 24..35: 32 cins x s=2

#define ASTRIDE 36
#define BSTRIDE 36
#define A_TILE_F (BM * ASTRIDE)     // 4608 floats
#define B_TILE_F (BN * BSTRIDE)     // 9216 floats
#define STAGE_F  (A_TILE_F + B_TILE_F)            // 13824 floats
#define SMEM_BYTES (NSTAGE * STAGE_F * 4)         // 221184

// scalar-tile permutation: k = step*8 + half*4 + qid -> pos = qid*8 + step*2 + half
__host__ __device__ __forceinline__ int kperm(int k) {
    return (k & 3) * 8 + ((k >> 3) << 1) + ((k >> 2) & 1);
}

// pre-converted (tf32) weights in the custom (tile,pos) K-order
__device__ float g_wperm[COUT * K_TOT];

__device__ __forceinline__ uint32_t smem_u32(const void* p) {
    uint32_t a;
    asm("{ .reg .u64 t; cvta.to.shared.u64 t, %1; cvt.u32.u64 %0, t; }" : "=r"(a) : "l"(p));
    return a;
}
__device__ __forceinline__ uint32_t to_tf32(float f) {
    uint32_t u;
    asm("cvt.rna.tf32.f32 %0, %1;" : "=r"(u) : "f"(f));
    return u;
}

#define CP_ASYNC4(dst, src, sz) \
    asm volatile("cp.async.ca.shared.global [%0], [%1], 4, %2;" \
                 :: "r"(dst), "l"(src), "r"(sz) : "memory")
#define CP_ASYNC8(dst, src, sz) \
    asm volatile("cp.async.ca.shared.global [%0], [%1], 8, %2;" \
                 :: "r"(dst), "l"(src), "r"(sz) : "memory")
#define CP_ASYNC16(dst, src) \
    asm volatile("cp.async.cg.shared.global [%0], [%1], 16;" \
                 :: "r"(dst), "l"(src) : "memory")
#define CP_COMMIT()  asm volatile("cp.async.commit_group;" ::: "memory")
#define CP_WAIT2()   asm volatile("cp.async.wait_group 2;"  ::: "memory")
#define CP_WAIT1()   asm volatile("cp.async.wait_group 1;"  ::: "memory")
#define CP_WAIT0()   asm volatile("cp.async.wait_group 0;"  ::: "memory")

__device__ __forceinline__ void mma_tf32(float& c0, float& c1, float& c2, float& c3,
                                         uint32_t a0, uint32_t a1, uint32_t a2, uint32_t a3,
                                         uint32_t b0, uint32_t b1) {
    asm volatile("mma.sync.aligned.m16n8k8.row.col.f32.tf32.tf32.f32 "
                 "{%0,%1,%2,%3}, {%4,%5,%6,%7}, {%8,%9}, {%0,%1,%2,%3};"
                 : "+f"(c0), "+f"(c1), "+f"(c2), "+f"(c3)
                 : "r"(a0), "r"(a1), "r"(a2), "r"(a3), "r"(b0), "r"(b1));
}

// ---------------- weight pre-convert into (tile,pos) order ----------------
__global__ void prep_weights_kernel(const float* __restrict__ w)
{
    const int idx = blockIdx.x * blockDim.x + threadIdx.x;
    if (idx < COUT * K_TOT) {
        const int n   = idx / K_TOT;
        const int k   = idx - n * K_TOT;   // original: cin*9 + rs
        const int cin = k / 9;
        const int rs  = k - cin * 9;
        const int r   = rs / 3;
        const int s   = rs - r * 3;
        int t, pos;
        if (s < 2) {                        // paired tiles
            t = r * 8 + (cin >> 4);
            const int p = cin & 15;
            pos = (p >> 2) * 8 + (p & 3) * 2 + s;
        } else {                            // scalar tiles (s == 2)
            t = PAIRED_TILES + r * 4 + (cin >> 5);
            pos = kperm(cin & 31);
        }
        g_wperm[n * K_TOT + t * 32 + pos] = __uint_as_float(to_tf32(w[idx]));
    }
}

// ---------------- main implicit-GEMM kernel ----------------
__global__ __launch_bounds__(NT, 1)
void conv_mma_tf32_kernel(const float* __restrict__ x,
                          float* __restrict__ out)
{
    extern __shared__ float sm[];
    const uint32_t sbase = smem_u32(sm);

    const int tid  = threadIdx.x;
    const int lane = tid & 31;
    const int wid  = tid >> 5;
    const int gid  = lane >> 2;     // 0..7
    const int qid  = lane & 3;      // 0..3
    const int warp_m = wid & 1;     // 0..1 -> m offset *64
    const int warp_n = wid >> 1;    // 0..3 -> n offset *64
    const int m0 = blockIdx.x * BM;

    // ---- A gather: thread owns m-row = tid&127, half h of 32-k tile ----
    const int  mRow = tid & 127;
    const int  h    = tid >> 7;     // 0 or 1
    const int  mG     = m0 + mRow;
    const bool mValid = (mG < M_TOT);
    const int  sz4    = mValid ? 4 : 0;
    const int  sz8    = mValid ? 8 : 0;
    const int  mc  = mValid ? mG : (M_TOT - 1);
    const int  bA  = mc / OPIX;
    const int  rA  = mc - bA * OPIX;
    const int  ohA = rA / OHW;
    const int  owA = rA - ohA * OHW;
    const float* xrow = x + (size_t)bA * CIN * INHW
                          + (size_t)(ohA * STRIDE) * W_IN + owA * STRIDE;

    auto load_a = [&](int buf, int kt) {
        const uint32_t dstrow = sbase + (uint32_t)(buf * STAGE_F + mRow * ASTRIDE) * 4u;
        if (kt < PAIRED_TILES) {
            // 16 cins x s{0,1}: 8 pairs per thread via cp.async.8
            const int r       = kt >> 3;
            const int cinbase = (kt & 7) * 16;
            const float* base = xrow + (size_t)cinbase * INHW + r * W_IN;   // s = 0
            #pragma unroll
            for (int pp = 0; pp < 8; pp++) {
                const int q   = 2 * h + (pp >> 2);       // qid
                const int v   = pp & 3;
                const int cof = q * 4 + v;               // cin offset in tile
                const int pos = q * 8 + v * 2;           // s=0 slot; s=1 adjacent
                CP_ASYNC8(dstrow + 4u * (uint32_t)pos, base + (size_t)cof * INHW, sz8);
            }
        } else {
            // 32 cins at s=2: 16 scalars per thread via cp.async.4
            const int j2      = kt - PAIRED_TILES;
            const int r       = j2 >> 2;
            const int cinbase = (j2 & 3) * 32;
            const float* base = xrow + (size_t)(cinbase + h * 16) * INHW + r * W_IN + 2;
            #pragma unroll
            for (int j = 0; j < 16; j++) {
                const int kl  = h * 16 + j;
                const int pos = (kl & 3) * 8 + ((kl >> 3) << 1) + ((kl >> 2) & 1);
                CP_ASYNC4(dstrow + 4u * (uint32_t)pos, base + (size_t)j * INHW, sz4);
            }
        }
    };
    auto load_b = [&](int buf, int kt) {
        #pragma unroll
        for (int p = 0; p < 8; p++) {
            const int idx = tid + NT * p;
            const int row = idx >> 3;          // 0..255
            const int q   = idx & 7;
            const float* g = g_wperm + (size_t)row * K_TOT + kt * BK + q * 4;
            const uint32_t dst = sbase +
                (uint32_t)(buf * STAGE_F + A_TILE_F + row * BSTRIDE + q * 4) * 4u;
            CP_ASYNC16(dst, g);
        }
    };

    float acc[4][8][4];
    #pragma unroll
    for (int i = 0; i < 4; i++)
        #pragma unroll
        for (int j = 0; j < 8; j++)
            #pragma unroll
            for (int e = 0; e < 4; e++)
                acc[i][j][e] = 0.0f;

    // ---- prologue: prime 3 of 4 stages ----
    load_a(0, 0); load_b(0, 0); CP_COMMIT();
    load_a(1, 1); load_b(1, 1); CP_COMMIT();
    load_a(2, 2); load_b(2, 2); CP_COMMIT();

    #pragma unroll 1
    for (int kt = 0; kt < KTILES; kt++) {
        const int buf = kt & 3;
        if (kt <= KTILES - 3)      CP_WAIT2();
        else if (kt == KTILES - 2) CP_WAIT1();
        else                       CP_WAIT0();
        __syncthreads();

        // issue next loads immediately (stage (kt+3)&3 was last read at kt-1;
        // the sync above orders all its readers before these writes)
        if (kt + 3 < KTILES) {
            load_a((kt + 3) & 3, kt + 3);
            load_b((kt + 3) & 3, kt + 3);
            CP_COMMIT();
        }

        const float* A  = sm + buf * STAGE_F;
        const float* Bt = A + A_TILE_F;

        #pragma unroll
        for (int sp = 0; sp < 2; sp++) {          // step pairs
            float4 av[4][2];
            #pragma unroll
            for (int mt = 0; mt < 4; mt++) {
                av[mt][0] = *(const float4*)(A + (warp_m * 64 + mt * 16 + gid) * ASTRIDE + qid * 8 + sp * 4);
                av[mt][1] = *(const float4*)(A + (warp_m * 64 + mt * 16 + gid + 8) * ASTRIDE + qid * 8 + sp * 4);
            }
            float4 bv[8];
            #pragma unroll
            for (int nt = 0; nt < 8; nt++)
                bv[nt] = *(const float4*)(Bt + (warp_n * 64 + nt * 8 + gid) * BSTRIDE + qid * 8 + sp * 4);

            #pragma unroll
            for (int mt = 0; mt < 4; mt++) {
                const uint32_t a0 = to_tf32(av[mt][0].x);
                const uint32_t a1 = to_tf32(av[mt][1].x);
                const uint32_t a2 = to_tf32(av[mt][0].y);
                const uint32_t a3 = to_tf32(av[mt][1].y);
                #pragma unroll
                for (int nt = 0; nt < 8; nt++)
                    mma_tf32(acc[mt][nt][0], acc[mt][nt][1], acc[mt][nt][2], acc[mt][nt][3],
                             a0, a1, a2, a3,
                             __float_as_uint(bv[nt].x), __float_as_uint(bv[nt].y));
            }
            #pragma unroll
            for (int mt = 0; mt < 4; mt++) {
                const uint32_t a0 = to_tf32(av[mt][0].z);
                const uint32_t a1 = to_tf32(av[mt][1].z);
                const uint32_t a2 = to_tf32(av[mt][0].w);
                const uint32_t a3 = to_tf32(av[mt][1].w);
                #pragma unroll
                for (int nt = 0; nt < 8; nt++)
                    mma_tf32(acc[mt][nt][0], acc[mt][nt][1], acc[mt][nt][2], acc[mt][nt][3],
                             a0, a1, a2, a3,
                             __float_as_uint(bv[nt].z), __float_as_uint(bv[nt].w));
            }
        }
    }

    // ---- epilogue: direct register -> gmem scatter ----
    #pragma unroll
    for (int mt = 0; mt < 4; mt++) {
        const int mb = m0 + warp_m * 64 + mt * 16;
        #pragma unroll
        for (int half = 0; half < 2; half++) {
            const int m = mb + gid + half * 8;
            if (m < M_TOT) {
                const int b2  = m / OPIX;
                const int r2  = m - b2 * OPIX;
                const int oh2 = r2 / OHW;
                const int ow2 = r2 - oh2 * OHW;
                float* op = out + (size_t)b2 * COUT * OPIX + (size_t)oh2 * OHW + ow2;
                const int ncol0 = warp_n * 64 + qid * 2;
                #pragma unroll
                for (int nt = 0; nt < 8; nt++) {
                    const int n = ncol0 + nt * 8;
                    op[(size_t)n * OPIX]       = acc[mt][nt][half * 2 + 0];
                    op[(size_t)(n + 1) * OPIX] = acc[mt][nt][half * 2 + 1];
                }
            }
        }
    }
}

extern "C" void kernel_launch(void* const* d_in, const int* in_sizes, int n_in,
                              void* d_out, int out_size)
{
    const float* x = (const float*)d_in[0];
    const float* w = (const float*)d_in[1];
    float* out = (float*)d_out;

    cudaFuncSetAttribute(conv_mma_tf32_kernel,
                         cudaFuncAttributeMaxDynamicSharedMemorySize, SMEM_BYTES);

    prep_weights_kernel<<<(COUT * K_TOT + 255) / 256, 256>>>(w);

    const int grid = (M_TOT + BM - 1) / BM;   // 757
    conv_mma_tf32_kernel<<<grid, NT, SMEM_BYTES>>>(x, out);
}

// round 14
// speedup vs baseline: 1.8733x; 1.0403x over previous
#include <cuda_runtime.h>
#include <cstdint>

// ---------------- problem constants ----------------
#define B_SZ   32
#define CIN    128
#define H_IN   112
#define W_IN   112
#define COUT   256
#define OHW    55
#define STRIDE 2
#define M_TOT  (B_SZ * OHW * OHW)   // 96800
#define K_TOT  (CIN * 9)            // 1152
#define OPIX   (OHW * OHW)          // 3025
#define INHW   (H_IN * W_IN)        // 12544

// ---------------- GEMM tiling ----------------
#define BM 128
#define BN 256
#define BK 32
#define NT 256
#define KTILES (K_TOT / BK)         // 36
#define NSTAGE 4
#define PAIRED_TILES 24             // tiles 0..23: 16 cins x s{0,1}; 24..35: 32 cins x s=2

#define ASTRIDE 36
#define BSTRIDE 36
#define A_TILE_F (BM * ASTRIDE)     // 4608 floats
#define B_TILE_F (BN * BSTRIDE)     // 9216 floats
#define STAGE_F  (A_TILE_F + B_TILE_F)            // 13824 floats
#define SMEM_BYTES (NSTAGE * STAGE_F * 4)         // 221184

// A-operand truncation-bias compensation: mma.tf32 truncates raw fp32 A
// (mean relative shrink 2^-11); pre-scale B by (1 + 2^-11) to cancel.
#define BIAS_COMP 1.00048828125f

// scalar-tile permutation: k = step*8 + half*4 + qid -> pos = qid*8 + step*2 + half
__host__ __device__ __forceinline__ int kperm(int k) {
    return (k & 3) * 8 + ((k >> 3) << 1) + ((k >> 2) & 1);
}

// pre-converted (tf32, bias-compensated) weights in the custom (tile,pos) K-order
__device__ float g_wperm[COUT * K_TOT];

__device__ __forceinline__ uint32_t smem_u32(const void* p) {
    uint32_t a;
    asm("{ .reg .u64 t; cvta.to.shared.u64 t, %1; cvt.u32.u64 %0, t; }" : "=r"(a) : "l"(p));
    return a;
}
__device__ __forceinline__ uint32_t to_tf32(float f) {
    uint32_t u;
    asm("cvt.rna.tf32.f32 %0, %1;" : "=r"(u) : "f"(f));
    return u;
}

#define CP_ASYNC4(dst, src, sz) \
    asm volatile("cp.async.ca.shared.global [%0], [%1], 4, %2;" \
                 :: "r"(dst), "l"(src), "r"(sz) : "memory")
#define CP_ASYNC8(dst, src, sz) \
    asm volatile("cp.async.ca.shared.global [%0], [%1], 8, %2;" \
                 :: "r"(dst), "l"(src), "r"(sz) : "memory")
#define CP_ASYNC16(dst, src) \
    asm volatile("cp.async.cg.shared.global [%0], [%1], 16;" \
                 :: "r"(dst), "l"(src) : "memory")
#define CP_COMMIT()  asm volatile("cp.async.commit_group;" ::: "memory")
#define CP_WAIT2()   asm volatile("cp.async.wait_group 2;"  ::: "memory")
#define CP_WAIT1()   asm volatile("cp.async.wait_group 1;"  ::: "memory")
#define CP_WAIT0()   asm volatile("cp.async.wait_group 0;"  ::: "memory")

__device__ __forceinline__ void mma_tf32(float& c0, float& c1, float& c2, float& c3,
                                         uint32_t a0, uint32_t a1, uint32_t a2, uint32_t a3,
                                         uint32_t b0, uint32_t b1) {
    asm volatile("mma.sync.aligned.m16n8k8.row.col.f32.tf32.tf32.f32 "
                 "{%0,%1,%2,%3}, {%4,%5,%6,%7}, {%8,%9}, {%0,%1,%2,%3};"
                 : "+f"(c0), "+f"(c1), "+f"(c2), "+f"(c3)
                 : "r"(a0), "r"(a1), "r"(a2), "r"(a3), "r"(b0), "r"(b1));
}

// ---------------- weight pre-convert into (tile,pos) order ----------------
__global__ void prep_weights_kernel(const float* __restrict__ w)
{
    const int idx = blockIdx.x * blockDim.x + threadIdx.x;
    if (idx < COUT * K_TOT) {
        const int n   = idx / K_TOT;
        const int k   = idx - n * K_TOT;   // original: cin*9 + rs
        const int cin = k / 9;
        const int rs  = k - cin * 9;
        const int r   = rs / 3;
        const int s   = rs - r * 3;
        int t, pos;
        if (s < 2) {                        // paired tiles
            t = r * 8 + (cin >> 4);
            const int p = cin & 15;
            pos = (p >> 2) * 8 + (p & 3) * 2 + s;
        } else {                            // scalar tiles (s == 2)
            t = PAIRED_TILES + r * 4 + (cin >> 5);
            pos = kperm(cin & 31);
        }
        g_wperm[n * K_TOT + t * 32 + pos] =
            __uint_as_float(to_tf32(w[idx] * BIAS_COMP));
    }
}

// ---------------- main implicit-GEMM kernel ----------------
__global__ __launch_bounds__(NT, 1)
void conv_mma_tf32_kernel(const float* __restrict__ x,
                          float* __restrict__ out)
{
    extern __shared__ float sm[];
    const uint32_t sbase = smem_u32(sm);

    const int tid  = threadIdx.x;
    const int lane = tid & 31;
    const int wid  = tid >> 5;
    const int gid  = lane >> 2;     // 0..7
    const int qid  = lane & 3;      // 0..3
    const int warp_m = wid & 1;     // 0..1 -> m offset *64
    const int warp_n = wid >> 1;    // 0..3 -> n offset *64
    const int m0 = blockIdx.x * BM;

    // ---- A gather: thread owns m-row = tid&127, half h of 32-k tile ----
    const int  mRow = tid & 127;
    const int  h    = tid >> 7;     // 0 or 1
    const int  mG     = m0 + mRow;
    const bool mValid = (mG < M_TOT);
    const int  sz4    = mValid ? 4 : 0;
    const int  sz8    = mValid ? 8 : 0;
    const int  mc  = mValid ? mG : (M_TOT - 1);
    const int  bA  = mc / OPIX;
    const int  rA  = mc - bA * OPIX;
    const int  ohA = rA / OHW;
    const int  owA = rA - ohA * OHW;
    const float* xrow = x + (size_t)bA * CIN * INHW
                          + (size_t)(ohA * STRIDE) * W_IN + owA * STRIDE;

    auto load_a = [&](int buf, int kt) {
        const uint32_t dstrow = sbase + (uint32_t)(buf * STAGE_F + mRow * ASTRIDE) * 4u;
        if (kt < PAIRED_TILES) {
            // 16 cins x s{0,1}: 8 pairs per thread via cp.async.8
            const int r       = kt >> 3;
            const int cinbase = (kt & 7) * 16;
            const float* base = xrow + (size_t)cinbase * INHW + r * W_IN;   // s = 0
            #pragma unroll
            for (int pp = 0; pp < 8; pp++) {
                const int q   = 2 * h + (pp >> 2);       // qid
                const int v   = pp & 3;
                const int cof = q * 4 + v;               // cin offset in tile
                const int pos = q * 8 + v * 2;           // s=0 slot; s=1 adjacent
                CP_ASYNC8(dstrow + 4u * (uint32_t)pos, base + (size_t)cof * INHW, sz8);
            }
        } else {
            // 32 cins at s=2: 16 scalars per thread via cp.async.4
            const int j2      = kt - PAIRED_TILES;
            const int r       = j2 >> 2;
            const int cinbase = (j2 & 3) * 32;
            const float* base = xrow + (size_t)(cinbase + h * 16) * INHW + r * W_IN + 2;
            #pragma unroll
            for (int j = 0; j < 16; j++) {
                const int kl  = h * 16 + j;
                const int pos = (kl & 3) * 8 + ((kl >> 3) << 1) + ((kl >> 2) & 1);
                CP_ASYNC4(dstrow + 4u * (uint32_t)pos, base + (size_t)j * INHW, sz4);
            }
        }
    };
    auto load_b = [&](int buf, int kt) {
        #pragma unroll
        for (int p = 0; p < 8; p++) {
            const int idx = tid + NT * p;
            const int row = idx >> 3;          // 0..255
            const int q   = idx & 7;
            const float* g = g_wperm + (size_t)row * K_TOT + kt * BK + q * 4;
            const uint32_t dst = sbase +
                (uint32_t)(buf * STAGE_F + A_TILE_F + row * BSTRIDE + q * 4) * 4u;
            CP_ASYNC16(dst, g);
        }
    };

    float acc[4][8][4];
    #pragma unroll
    for (int i = 0; i < 4; i++)
        #pragma unroll
        for (int j = 0; j < 8; j++)
            #pragma unroll
            for (int e = 0; e < 4; e++)
                acc[i][j][e] = 0.0f;

    // ---- prologue: prime 3 of 4 stages ----
    load_a(0, 0); load_b(0, 0); CP_COMMIT();
    load_a(1, 1); load_b(1, 1); CP_COMMIT();
    load_a(2, 2); load_b(2, 2); CP_COMMIT();

    #pragma unroll 1
    for (int kt = 0; kt < KTILES; kt++) {
        const int buf = kt & 3;
        if (kt <= KTILES - 3)      CP_WAIT2();
        else if (kt == KTILES - 2) CP_WAIT1();
        else                       CP_WAIT0();
        __syncthreads();

        // issue next loads immediately (stage (kt+3)&3 was last read at kt-1;
        // the sync above orders all its readers before these writes)
        if (kt + 3 < KTILES) {
            load_a((kt + 3) & 3, kt + 3);
            load_b((kt + 3) & 3, kt + 3);
            CP_COMMIT();
        }

        const float* A  = sm + buf * STAGE_F;
        const float* Bt = A + A_TILE_F;

        #pragma unroll
        for (int sp = 0; sp < 2; sp++) {          // step pairs
            uint4 av[4][2];
            #pragma unroll
            for (int mt = 0; mt < 4; mt++) {
                av[mt][0] = *(const uint4*)(A + (warp_m * 64 + mt * 16 + gid) * ASTRIDE + qid * 8 + sp * 4);
                av[mt][1] = *(const uint4*)(A + (warp_m * 64 + mt * 16 + gid + 8) * ASTRIDE + qid * 8 + sp * 4);
            }
            uint4 bv[8];
            #pragma unroll
            for (int nt = 0; nt < 8; nt++)
                bv[nt] = *(const uint4*)(Bt + (warp_n * 64 + nt * 8 + gid) * BSTRIDE + qid * 8 + sp * 4);

            // raw fp32 bits as tf32 A operands (HW truncation; bias folded into B)
            #pragma unroll
            for (int mt = 0; mt < 4; mt++) {
                #pragma unroll
                for (int nt = 0; nt < 8; nt++)
                    mma_tf32(acc[mt][nt][0], acc[mt][nt][1], acc[mt][nt][2], acc[mt][nt][3],
                             av[mt][0].x, av[mt][1].x, av[mt][0].y, av[mt][1].y,
                             bv[nt].x, bv[nt].y);
            }
            #pragma unroll
            for (int mt = 0; mt < 4; mt++) {
                #pragma unroll
                for (int nt = 0; nt < 8; nt++)
                    mma_tf32(acc[mt][nt][0], acc[mt][nt][1], acc[mt][nt][2], acc[mt][nt][3],
                             av[mt][0].z, av[mt][1].z, av[mt][0].w, av[mt][1].w,
                             bv[nt].z, bv[nt].w);
            }
        }
    }

    // ---- epilogue: direct register -> gmem scatter ----
    #pragma unroll
    for (int mt = 0; mt < 4; mt++) {
        const int mb = m0 + warp_m * 64 + mt * 16;
        #pragma unroll
        for (int half = 0; half < 2; half++) {
            const int m = mb + gid + half * 8;
            if (m < M_TOT) {
                const int b2  = m / OPIX;
                const int r2  = m - b2 * OPIX;
                const int oh2 = r2 / OHW;
                const int ow2 = r2 - oh2 * OHW;
                float* op = out + (size_t)b2 * COUT * OPIX + (size_t)oh2 * OHW + ow2;
                const int ncol0 = warp_n * 64 + qid * 2;
                #pragma unroll
                for (int nt = 0; nt < 8; nt++) {
                    const int n = ncol0 + nt * 8;
                    op[(size_t)n * OPIX]       = acc[mt][nt][half * 2 + 0];
                    op[(size_t)(n + 1) * OPIX] = acc[mt][nt][half * 2 + 1];
                }
            }
        }
    }
}

extern "C" void kernel_launch(void* const* d_in, const int* in_sizes, int n_in,
                              void* d_out, int out_size)
{
    const float* x = (const float*)d_in[0];
    const float* w = (const float*)d_in[1];
    float* out = (float*)d_out;

    cudaFuncSetAttribute(conv_mma_tf32_kernel,
                         cudaFuncAttributeMaxDynamicSharedMemorySize, SMEM_BYTES);

    prep_weights_kernel<<<(COUT * K_TOT + 255) / 256, 256>>>(w);

    const int grid = (M_TOT + BM - 1) / BM;   // 757
    conv_mma_tf32_kernel<<<grid, NT, SMEM_BYTES>>>(x, out);
}